// round 11
// baseline (speedup 1.0000x reference)
#include <cuda_runtime.h>
#include <cuda_bf16.h>
#include <cstdint>

typedef unsigned long long ull;

__device__ __forceinline__ ull pack2(float lo, float hi) {
    ull r; asm("mov.b64 %0, {%1, %2};" : "=l"(r) : "f"(lo), "f"(hi)); return r;
}
__device__ __forceinline__ void unpack2(ull v, float& lo, float& hi) {
    asm("mov.b64 {%0, %1}, %2;" : "=f"(lo), "=f"(hi) : "l"(v));
}
__device__ __forceinline__ ull fma2(ull a, ull b, ull c) {
    ull d; asm("fma.rn.f32x2 %0, %1, %2, %3;" : "=l"(d) : "l"(a), "l"(b), "l"(c)); return d;
}
__device__ __forceinline__ float softplus_f(float x) {
    return fmaxf(x, 0.0f) + log1pf(expf(-fabsf(x)));
}
__device__ __forceinline__ uint32_t smem_u32(const void* p) {
    uint32_t a;
    asm("{ .reg .u64 t; cvta.to.shared.u64 t, %1; cvt.u32.u64 %0, t; }" : "=r"(a) : "l"(p));
    return a;
}

#define SW128(off) ((off) ^ (((off) >> 3) & 0x70))

// mma.sync m16n8k16 row.col f32 += bf16*bf16 (baseline PTX, works on compute_103)
#define MMA16816(d, a, b0v, b1v) \
    asm volatile("mma.sync.aligned.m16n8k16.row.col.f32.bf16.bf16.f32 " \
        "{%0,%1,%2,%3}, {%4,%5,%6,%7}, {%8,%9}, {%0,%1,%2,%3};" \
        : "+f"((d)[0]), "+f"((d)[1]), "+f"((d)[2]), "+f"((d)[3]) \
        : "r"((a)[0]), "r"((a)[1]), "r"((a)[2]), "r"((a)[3]), "r"(b0v), "r"(b1v))

static constexpr int DYN_SMEM = 1024 + 2 * 8192;   // align pad + W2hi + W2lo (SW128)

__global__ __launch_bounds__(128, 3)
void dln_mma(const float4* __restrict__ x,
             const float* __restrict__ W1, const float* __restrict__ b1,
             const float* __restrict__ W2, const float* __restrict__ b2,
             const float* __restrict__ WLd, const float* __restrict__ bLd,
             const float* __restrict__ WLo, const float* __restrict__ bLo,
             float4* __restrict__ out, int n)
{
    extern __shared__ char dyn[];
    __shared__ __align__(16) ulonglong2 sW1a[32], sW1b[32];  // (W1[2jp][k],W1[2jp+1][k]) pairs
    __shared__ ull sb1p[32];
    __shared__ ull sB2p[32];                                 // (b2[2jp], b2[2jp+1])
    __shared__ __align__(16) ulonglong2 sHd[32];             // {(Ld0 pair), (Ld1 pair)}
    __shared__ ull sLoP[32];                                 // (WLo pair)
    __shared__ float sbh[4];

    const int tid  = threadIdx.x;
    const int wid  = tid >> 5;
    const int lane = tid & 31;
    const int c    = lane & 3;    // quad col id
    const int rq   = lane >> 2;   // quad row id

    const uint32_t dbase = smem_u32(dyn);
    const uint32_t whi = (dbase + 1023u) & ~1023u;
    const uint32_t wlo = whi + 8192u;

    // ---- prep: W2 -> bf16 hi/lo SW128 tiles; packed small weights ----
    for (int i = tid; i < 4096; i += 128) {
        float w = W2[i];
        uint16_t hb; asm("cvt.rn.bf16.f32 %0, %1;" : "=h"(hb) : "f"(w));
        float hf = __uint_as_float(((uint32_t)hb) << 16);
        float lf = w - hf;
        uint16_t lb; asm("cvt.rn.bf16.f32 %0, %1;" : "=h"(lb) : "f"(lf));
        uint32_t off = SW128((uint32_t)(((i >> 6) * 128) + ((i & 63) * 2)));
        asm volatile("st.shared.u16 [%0], %1;" :: "r"(whi + off), "h"(hb));
        asm volatile("st.shared.u16 [%0], %1;" :: "r"(wlo + off), "h"(lb));
    }
    for (int jp = tid; jp < 32; jp += 128) {
        sW1a[jp] = make_ulonglong2(pack2(W1[(2*jp)*4+0], W1[(2*jp+1)*4+0]),
                                   pack2(W1[(2*jp)*4+1], W1[(2*jp+1)*4+1]));
        sW1b[jp] = make_ulonglong2(pack2(W1[(2*jp)*4+2], W1[(2*jp+1)*4+2]),
                                   pack2(W1[(2*jp)*4+3], W1[(2*jp+1)*4+3]));
        sb1p[jp] = pack2(b1[2*jp], b1[2*jp+1]);
        sB2p[jp] = pack2(b2[2*jp], b2[2*jp+1]);
        sHd[jp]  = make_ulonglong2(pack2(WLd[2*jp],    WLd[2*jp+1]),
                                   pack2(WLd[64+2*jp], WLd[64+2*jp+1]));
        sLoP[jp] = pack2(WLo[2*jp], WLo[2*jp+1]);
    }
    if (tid == 0) { sbh[0] = bLd[0]; sbh[1] = bLd[1]; sbh[2] = bLo[0]; sbh[3] = 0.f; }
    __syncthreads();

    const ull SLOPE2 = pack2(0.01f, 0.01f);
    const int ntiles = (n + 127) >> 7;
    const int tstep  = gridDim.x;

    // ---- prologue: load q for first tile ----
    int t = blockIdx.x;
    ull qp[16];
    {
        const int gb = (t << 7) + (wid << 5);
        #pragma unroll
        for (int s = 0; s < 4; ++s) {
            int gr = gb + rq + 8 * s;
            if (gr > n - 1) gr = n - 1;
            float4 q = x[gr];
            qp[4*s+0] = pack2(q.x, q.x);
            qp[4*s+1] = pack2(q.y, q.y);
            qp[4*s+2] = pack2(q.z, q.z);
            qp[4*s+3] = pack2(q.w, q.w);
        }
    }

    while (t < ntiles) {
        const int gbase = (t << 7) + (wid << 5);   // current tile rows (before prefetch)

        // ---- D init = broadcast b2 (MMA accumulates onto it) ----
        float D[2][8][4];
        #pragma unroll
        for (int nt = 0; nt < 8; ++nt) {
            float e0, e1; unpack2(sB2p[4*nt + c], e0, e1);
            D[0][nt][0] = e0; D[0][nt][1] = e1; D[0][nt][2] = e0; D[0][nt][3] = e1;
            D[1][nt][0] = e0; D[1][nt][1] = e1; D[1][nt][2] = e0; D[1][nt][3] = e1;
        }

        #pragma unroll
        for (int kt = 0; kt < 4; ++kt) {
            // ---- A fragments in place: layer-1 fp32 + exact bf16 hi/lo split ----
            uint32_t ahi[2][4], alo[2][4];
            #pragma unroll
            for (int h = 0; h < 2; ++h) {
                int jp = c + 8 * kt + 4 * h;
                ulonglong2 wA = sW1a[jp], wB = sW1b[jp];
                ull bb = sb1p[jp];
                #pragma unroll
                for (int s = 0; s < 4; ++s) {
                    ull z = fma2(wA.x, qp[4*s+0], bb);
                    z = fma2(wA.y, qp[4*s+1], z);
                    z = fma2(wB.x, qp[4*s+2], z);
                    z = fma2(wB.y, qp[4*s+3], z);
                    ull mm = fma2(z, SLOPE2, 0ull);        // 0.01*z packed
                    float z0, z1, m0, m1;
                    unpack2(z, z0, z1); unpack2(mm, m0, m1);
                    float e = fmaxf(z0, m0), o = fmaxf(z1, m1);
                    uint32_t hv;
                    asm("cvt.rn.bf16x2.f32 %0, %1, %2;" : "=r"(hv) : "f"(o), "f"(e));
                    float ef = __uint_as_float(hv << 16);
                    float of = __uint_as_float(hv & 0xFFFF0000u);
                    float le = e - ef, lod = o - of;       // exact residuals
                    uint32_t lv;
                    asm("cvt.rn.bf16x2.f32 %0, %1, %2;" : "=r"(lv) : "f"(lod), "f"(le));
                    int m = s >> 1, half = s & 1;
                    ahi[m][2*h + half] = hv;
                    alo[m][2*h + half] = lv;
                }
            }

            // ---- B via ldmatrix; 3-product MMA, 4 independent accumulators interleaved ----
            #pragma unroll
            for (int p = 0; p < 4; ++p) {
                int mat = lane >> 3, rin = lane & 7;
                int nrow = (2*p + (mat >> 1)) * 8 + rin;
                int kseg = 2*kt + (mat & 1);
                uint32_t off = SW128((uint32_t)(nrow * 128 + kseg * 16));
                uint32_t bh0, bh1, bh2, bh3, bl0, bl1, bl2, bl3;
                asm volatile("ldmatrix.sync.aligned.m8n8.x4.shared.b16 {%0,%1,%2,%3}, [%4];"
                    : "=r"(bh0), "=r"(bh1), "=r"(bh2), "=r"(bh3) : "r"(whi + off));
                asm volatile("ldmatrix.sync.aligned.m8n8.x4.shared.b16 {%0,%1,%2,%3}, [%4];"
                    : "=r"(bl0), "=r"(bl1), "=r"(bl2), "=r"(bl3) : "r"(wlo + off));
                // pass 1: hi*hi  (RAW distance 4)
                MMA16816(D[0][2*p],     ahi[0], bh0, bh1);
                MMA16816(D[1][2*p],     ahi[1], bh0, bh1);
                MMA16816(D[0][2*p + 1], ahi[0], bh2, bh3);
                MMA16816(D[1][2*p + 1], ahi[1], bh2, bh3);
                // pass 2: hi*lo
                MMA16816(D[0][2*p],     ahi[0], bl0, bl1);
                MMA16816(D[1][2*p],     ahi[1], bl0, bl1);
                MMA16816(D[0][2*p + 1], ahi[0], bl2, bl3);
                MMA16816(D[1][2*p + 1], ahi[1], bl2, bl3);
                // pass 3: lo*hi
                MMA16816(D[0][2*p],     alo[0], bh0, bh1);
                MMA16816(D[1][2*p],     alo[1], bh0, bh1);
                MMA16816(D[0][2*p + 1], alo[0], bh2, bh3);
                MMA16816(D[1][2*p + 1], alo[1], bh2, bh3);
            }
        }

        // ---- prefetch next tile's q NOW; epilogue below hides the LDG latency ----
        const int tn = t + tstep;
        if (tn < ntiles) {
            const int gb = (tn << 7) + (wid << 5);
            #pragma unroll
            for (int s = 0; s < 4; ++s) {
                int gr = gb + rq + 8 * s;
                if (gr > n - 1) gr = n - 1;
                float4 q = x[gr];
                qp[4*s+0] = pack2(q.x, q.x);
                qp[4*s+1] = pack2(q.y, q.y);
                qp[4*s+2] = pack2(q.z, q.z);
                qp[4*s+3] = pack2(q.w, q.w);
            }
        }

        // ---- packed epilogue: leaky + head dots over column pairs ----
        float rLd0[4], rLd1[4], rLo[4];
        #pragma unroll
        for (int m = 0; m < 2; ++m) {
            ull a0_0 = 0ull, a1_0 = 0ull, a2_0 = 0ull;   // row slot 2m
            ull a0_1 = 0ull, a1_1 = 0ull, a2_1 = 0ull;   // row slot 2m+1
            #pragma unroll
            for (int nt = 0; nt < 8; ++nt) {
                int jp = 4*nt + c;
                ulonglong2 hd = sHd[jp];
                ull lop = sLoP[jp];
                {
                    ull p = pack2(D[m][nt][0], D[m][nt][1]);
                    ull mm = fma2(p, SLOPE2, 0ull);
                    float z0, z1, m0, m1;
                    unpack2(p, z0, z1); unpack2(mm, m0, m1);
                    ull hp = pack2(fmaxf(z0, m0), fmaxf(z1, m1));
                    a0_0 = fma2(hd.x, hp, a0_0);
                    a1_0 = fma2(hd.y, hp, a1_0);
                    a2_0 = fma2(lop,  hp, a2_0);
                }
                {
                    ull p = pack2(D[m][nt][2], D[m][nt][3]);
                    ull mm = fma2(p, SLOPE2, 0ull);
                    float z0, z1, m0, m1;
                    unpack2(p, z0, z1); unpack2(mm, m0, m1);
                    ull hp = pack2(fmaxf(z0, m0), fmaxf(z1, m1));
                    a0_1 = fma2(hd.x, hp, a0_1);
                    a1_1 = fma2(hd.y, hp, a1_1);
                    a2_1 = fma2(lop,  hp, a2_1);
                }
            }
            float u, v;
            unpack2(a0_0, u, v); rLd0[2*m]   = u + v;
            unpack2(a1_0, u, v); rLd1[2*m]   = u + v;
            unpack2(a2_0, u, v); rLo[2*m]    = u + v;
            unpack2(a0_1, u, v); rLd0[2*m+1] = u + v;
            unpack2(a1_1, u, v); rLd1[2*m+1] = u + v;
            unpack2(a2_1, u, v); rLo[2*m+1]  = u + v;
        }

        // ---- quad all-reduce; lane c finalizes row rq + 8c ----
        float v0 = 0.f, v1 = 0.f, v2 = 0.f;
        #pragma unroll
        for (int s = 0; s < 4; ++s) {
            float a0 = rLd0[s], a1 = rLd1[s], a2 = rLo[s];
            #pragma unroll
            for (int msk = 1; msk <= 2; msk <<= 1) {
                a0 += __shfl_xor_sync(0xFFFFFFFFu, a0, msk);
                a1 += __shfl_xor_sync(0xFFFFFFFFu, a1, msk);
                a2 += __shfl_xor_sync(0xFFFFFFFFu, a2, msk);
            }
            if (c == s) { v0 = a0; v1 = a1; v2 = a2; }
        }

        int g = gbase + rq + 8 * c;
        if (g < n) {
            float Ld0 = softplus_f(v0 + sbh[0]);
            float Ld1 = softplus_f(v1 + sbh[1]);
            float Lo  = v2 + sbh[2];
            float H00 = fmaf(Ld0, Ld0, 1e-9f);
            float H01 = Ld0 * Lo;
            float H11 = fmaf(Lo, Lo, fmaf(Ld1, Ld1, 1e-9f));
            out[g] = make_float4(H00, H01, H01, H11);
        }

        t = tn;
    }
}

extern "C" void kernel_launch(void* const* d_in, const int* in_sizes, int n_in,
                              void* d_out, int out_size) {
    const float4* x  = (const float4*)d_in[0];
    const float* W1  = (const float*)d_in[1];
    const float* b1  = (const float*)d_in[2];
    const float* W2  = (const float*)d_in[3];
    const float* b2  = (const float*)d_in[4];
    const float* WLd = (const float*)d_in[5];
    const float* bLd = (const float*)d_in[6];
    const float* WLo = (const float*)d_in[7];
    const float* bLo = (const float*)d_in[8];

    int n = in_sizes[0] / 4;
    int ntiles = (n + 127) >> 7;
    int blocks = 456;                  // 3 CTAs x 152 SMs persistent; ~18 tiles/CTA
    if (blocks > ntiles) blocks = ntiles;
    dln_mma<<<blocks, 128, DYN_SMEM>>>(x, W1, b1, W2, b2, WLd, bLd, WLo, bLo,
                                       (float4*)d_out, n);
}

// round 12
// speedup vs baseline: 1.5535x; 1.5535x over previous
#include <cuda_runtime.h>
#include <cuda_bf16.h>
#include <cstdint>

typedef unsigned long long ull;

__device__ __forceinline__ ull pack2(float lo, float hi) {
    ull r; asm("mov.b64 %0, {%1, %2};" : "=l"(r) : "f"(lo), "f"(hi)); return r;
}
__device__ __forceinline__ void unpack2(ull v, float& lo, float& hi) {
    asm("mov.b64 {%0, %1}, %2;" : "=f"(lo), "=f"(hi) : "l"(v));
}
__device__ __forceinline__ ull fma2(ull a, ull b, ull c) {
    ull d; asm("fma.rn.f32x2 %0, %1, %2, %3;" : "=l"(d) : "l"(a), "l"(b), "l"(c)); return d;
}
__device__ __forceinline__ float softplus_f(float x) {
    return fmaxf(x, 0.0f) + log1pf(expf(-fabsf(x)));
}
__device__ __forceinline__ uint32_t smem_u32(const void* p) {
    uint32_t a;
    asm("{ .reg .u64 t; cvta.to.shared.u64 t, %1; cvt.u32.u64 %0, t; }" : "=r"(a) : "l"(p));
    return a;
}

#define SW128(off) ((off) ^ (((off) >> 3) & 0x70))

// mma.sync m16n8k16 row.col f32 += bf16*bf16 (baseline PTX, works on compute_103)
#define MMA16816(d, a, b0v, b1v) \
    asm volatile("mma.sync.aligned.m16n8k16.row.col.f32.bf16.bf16.f32 " \
        "{%0,%1,%2,%3}, {%4,%5,%6,%7}, {%8,%9}, {%0,%1,%2,%3};" \
        : "+f"((d)[0]), "+f"((d)[1]), "+f"((d)[2]), "+f"((d)[3]) \
        : "r"((a)[0]), "r"((a)[1]), "r"((a)[2]), "r"((a)[3]), "r"(b0v), "r"(b1v))

static constexpr int DYN_SMEM = 1024 + 2 * 8192;   // align pad + W2hi + W2lo (SW128)

__global__ __launch_bounds__(128, 4)
void dln_mma(const float4* __restrict__ x,
             const float* __restrict__ W1, const float* __restrict__ b1,
             const float* __restrict__ W2, const float* __restrict__ b2,
             const float* __restrict__ WLd, const float* __restrict__ bLd,
             const float* __restrict__ WLo, const float* __restrict__ bLo,
             float4* __restrict__ out, int n)
{
    extern __shared__ char dyn[];
    __shared__ __align__(16) ulonglong2 sW1a[32], sW1b[32];  // (W1[2jp][k],W1[2jp+1][k]) pairs
    __shared__ ull sb1p[32];
    __shared__ ull sB2p[32];                                 // (b2[2jp], b2[2jp+1])
    __shared__ __align__(16) ulonglong2 sHd[32];             // {(Ld0 pair), (Ld1 pair)}
    __shared__ ull sLoP[32];                                 // (WLo pair)
    __shared__ float sbh[4];

    const int tid  = threadIdx.x;
    const int wid  = tid >> 5;
    const int lane = tid & 31;
    const int c    = lane & 3;    // quad col id
    const int rq   = lane >> 2;   // quad row id

    const uint32_t dbase = smem_u32(dyn);
    const uint32_t whi = (dbase + 1023u) & ~1023u;
    const uint32_t wlo = whi + 8192u;

    // ---- prep: W2 -> bf16 hi/lo SW128 tiles; packed small weights ----
    for (int i = tid; i < 4096; i += 128) {
        float w = W2[i];
        uint16_t hb; asm("cvt.rn.bf16.f32 %0, %1;" : "=h"(hb) : "f"(w));
        float hf = __uint_as_float(((uint32_t)hb) << 16);
        float lf = w - hf;
        uint16_t lb; asm("cvt.rn.bf16.f32 %0, %1;" : "=h"(lb) : "f"(lf));
        uint32_t off = SW128((uint32_t)(((i >> 6) * 128) + ((i & 63) * 2)));
        asm volatile("st.shared.u16 [%0], %1;" :: "r"(whi + off), "h"(hb));
        asm volatile("st.shared.u16 [%0], %1;" :: "r"(wlo + off), "h"(lb));
    }
    for (int jp = tid; jp < 32; jp += 128) {
        sW1a[jp] = make_ulonglong2(pack2(W1[(2*jp)*4+0], W1[(2*jp+1)*4+0]),
                                   pack2(W1[(2*jp)*4+1], W1[(2*jp+1)*4+1]));
        sW1b[jp] = make_ulonglong2(pack2(W1[(2*jp)*4+2], W1[(2*jp+1)*4+2]),
                                   pack2(W1[(2*jp)*4+3], W1[(2*jp+1)*4+3]));
        sb1p[jp] = pack2(b1[2*jp], b1[2*jp+1]);
        sB2p[jp] = pack2(b2[2*jp], b2[2*jp+1]);
        sHd[jp]  = make_ulonglong2(pack2(WLd[2*jp],    WLd[2*jp+1]),
                                   pack2(WLd[64+2*jp], WLd[64+2*jp+1]));
        sLoP[jp] = pack2(WLo[2*jp], WLo[2*jp+1]);
    }
    if (tid == 0) { sbh[0] = bLd[0]; sbh[1] = bLd[1]; sbh[2] = bLo[0]; sbh[3] = 0.f; }
    __syncthreads();

    const ull SLOPE2 = pack2(0.01f, 0.01f);

    const int ntiles = (n + 127) >> 7;
    for (int t = blockIdx.x; t < ntiles; t += gridDim.x) {
        const int gbase = (t << 7) + (wid << 5);

        // ---- per-thread q rows (rq + 8s), stored UNPACKED (16 regs, not 32) ----
        float qv[16];
        #pragma unroll
        for (int s = 0; s < 4; ++s) {
            int gr = gbase + rq + 8 * s;
            if (gr > n - 1) gr = n - 1;
            float4 q = x[gr];
            qv[4*s+0] = q.x; qv[4*s+1] = q.y; qv[4*s+2] = q.z; qv[4*s+3] = q.w;
        }

        // ---- D init = broadcast b2 (MMA accumulates onto it) ----
        float D[2][8][4];
        #pragma unroll
        for (int nt = 0; nt < 8; ++nt) {
            float e0, e1; unpack2(sB2p[4*nt + c], e0, e1);
            D[0][nt][0] = e0; D[0][nt][1] = e1; D[0][nt][2] = e0; D[0][nt][3] = e1;
            D[1][nt][0] = e0; D[1][nt][1] = e1; D[1][nt][2] = e0; D[1][nt][3] = e1;
        }

        #pragma unroll
        for (int kt = 0; kt < 4; ++kt) {
            // ---- A fragments in place: layer-1 fp32 + exact bf16 hi/lo split ----
            uint32_t ahi[2][4], alo[2][4];
            #pragma unroll
            for (int h = 0; h < 2; ++h) {
                int jp = c + 8 * kt + 4 * h;
                ulonglong2 wA = sW1a[jp], wB = sW1b[jp];
                ull bb = sb1p[jp];
                #pragma unroll
                for (int s = 0; s < 4; ++s) {
                    ull z = fma2(wA.x, pack2(qv[4*s+0], qv[4*s+0]), bb);
                    z = fma2(wA.y, pack2(qv[4*s+1], qv[4*s+1]), z);
                    z = fma2(wB.x, pack2(qv[4*s+2], qv[4*s+2]), z);
                    z = fma2(wB.y, pack2(qv[4*s+3], qv[4*s+3]), z);
                    ull mm = fma2(z, SLOPE2, 0ull);        // 0.01*z packed
                    float z0, z1, m0, m1;
                    unpack2(z, z0, z1); unpack2(mm, m0, m1);
                    float e = fmaxf(z0, m0), o = fmaxf(z1, m1);
                    uint32_t hv;
                    asm("cvt.rn.bf16x2.f32 %0, %1, %2;" : "=r"(hv) : "f"(o), "f"(e));
                    float ef = __uint_as_float(hv << 16);
                    float of = __uint_as_float(hv & 0xFFFF0000u);
                    float le = e - ef, lod = o - of;       // exact residuals
                    uint32_t lv;
                    asm("cvt.rn.bf16x2.f32 %0, %1, %2;" : "=r"(lv) : "f"(lod), "f"(le));
                    int m = s >> 1, half = s & 1;
                    ahi[m][2*h + half] = hv;
                    alo[m][2*h + half] = lv;
                }
            }

            // ---- B via ldmatrix, 3-product compensated MMA (R10 ordering) ----
            #pragma unroll
            for (int p = 0; p < 4; ++p) {
                int mat = lane >> 3, rin = lane & 7;
                int nrow = (2*p + (mat >> 1)) * 8 + rin;
                int kseg = 2*kt + (mat & 1);
                uint32_t off = SW128((uint32_t)(nrow * 128 + kseg * 16));
                uint32_t bh0, bh1, bh2, bh3, bl0, bl1, bl2, bl3;
                asm volatile("ldmatrix.sync.aligned.m8n8.x4.shared.b16 {%0,%1,%2,%3}, [%4];"
                    : "=r"(bh0), "=r"(bh1), "=r"(bh2), "=r"(bh3) : "r"(whi + off));
                asm volatile("ldmatrix.sync.aligned.m8n8.x4.shared.b16 {%0,%1,%2,%3}, [%4];"
                    : "=r"(bl0), "=r"(bl1), "=r"(bl2), "=r"(bl3) : "r"(wlo + off));
                #pragma unroll
                for (int m = 0; m < 2; ++m) {
                    MMA16816(D[m][2*p],     ahi[m], bh0, bh1);
                    MMA16816(D[m][2*p],     ahi[m], bl0, bl1);
                    MMA16816(D[m][2*p],     alo[m], bh0, bh1);
                    MMA16816(D[m][2*p + 1], ahi[m], bh2, bh3);
                    MMA16816(D[m][2*p + 1], ahi[m], bl2, bl3);
                    MMA16816(D[m][2*p + 1], alo[m], bh2, bh3);
                }
            }
        }

        // ---- packed epilogue: leaky + head dots over column pairs ----
        float rLd0[4], rLd1[4], rLo[4];
        #pragma unroll
        for (int m = 0; m < 2; ++m) {
            ull a0_0 = 0ull, a1_0 = 0ull, a2_0 = 0ull;   // row slot 2m
            ull a0_1 = 0ull, a1_1 = 0ull, a2_1 = 0ull;   // row slot 2m+1
            #pragma unroll
            for (int nt = 0; nt < 8; ++nt) {
                int jp = 4*nt + c;
                ulonglong2 hd = sHd[jp];
                ull lop = sLoP[jp];
                {
                    ull p = pack2(D[m][nt][0], D[m][nt][1]);
                    ull mm = fma2(p, SLOPE2, 0ull);
                    float z0, z1, m0, m1;
                    unpack2(p, z0, z1); unpack2(mm, m0, m1);
                    ull hp = pack2(fmaxf(z0, m0), fmaxf(z1, m1));
                    a0_0 = fma2(hd.x, hp, a0_0);
                    a1_0 = fma2(hd.y, hp, a1_0);
                    a2_0 = fma2(lop,  hp, a2_0);
                }
                {
                    ull p = pack2(D[m][nt][2], D[m][nt][3]);
                    ull mm = fma2(p, SLOPE2, 0ull);
                    float z0, z1, m0, m1;
                    unpack2(p, z0, z1); unpack2(mm, m0, m1);
                    ull hp = pack2(fmaxf(z0, m0), fmaxf(z1, m1));
                    a0_1 = fma2(hd.x, hp, a0_1);
                    a1_1 = fma2(hd.y, hp, a1_1);
                    a2_1 = fma2(lop,  hp, a2_1);
                }
            }
            float u, v;
            unpack2(a0_0, u, v); rLd0[2*m]   = u + v;
            unpack2(a1_0, u, v); rLd1[2*m]   = u + v;
            unpack2(a2_0, u, v); rLo[2*m]    = u + v;
            unpack2(a0_1, u, v); rLd0[2*m+1] = u + v;
            unpack2(a1_1, u, v); rLd1[2*m+1] = u + v;
            unpack2(a2_1, u, v); rLo[2*m+1]  = u + v;
        }

        // ---- quad all-reduce; lane c finalizes row rq + 8c ----
        float v0 = 0.f, v1 = 0.f, v2 = 0.f;
        #pragma unroll
        for (int s = 0; s < 4; ++s) {
            float a0 = rLd0[s], a1 = rLd1[s], a2 = rLo[s];
            #pragma unroll
            for (int msk = 1; msk <= 2; msk <<= 1) {
                a0 += __shfl_xor_sync(0xFFFFFFFFu, a0, msk);
                a1 += __shfl_xor_sync(0xFFFFFFFFu, a1, msk);
                a2 += __shfl_xor_sync(0xFFFFFFFFu, a2, msk);
            }
            if (c == s) { v0 = a0; v1 = a1; v2 = a2; }
        }

        int g = gbase + rq + 8 * c;
        if (g < n) {
            float Ld0 = softplus_f(v0 + sbh[0]);
            float Ld1 = softplus_f(v1 + sbh[1]);
            float Lo  = v2 + sbh[2];
            float H00 = fmaf(Ld0, Ld0, 1e-9f);
            float H01 = Ld0 * Lo;
            float H11 = fmaf(Lo, Lo, fmaf(Ld1, Ld1, 1e-9f));
            out[g] = make_float4(H00, H01, H01, H11);
        }
    }
}

extern "C" void kernel_launch(void* const* d_in, const int* in_sizes, int n_in,
                              void* d_out, int out_size) {
    const float4* x  = (const float4*)d_in[0];
    const float* W1  = (const float*)d_in[1];
    const float* b1  = (const float*)d_in[2];
    const float* W2  = (const float*)d_in[3];
    const float* b2  = (const float*)d_in[4];
    const float* WLd = (const float*)d_in[5];
    const float* bLd = (const float*)d_in[6];
    const float* WLo = (const float*)d_in[7];
    const float* bLo = (const float*)d_in[8];

    int n = in_sizes[0] / 4;
    int ntiles = (n + 127) >> 7;
    int blocks = 608;                  // 4 CTAs x 152 SMs persistent
    if (blocks > ntiles) blocks = ntiles;
    dln_mma<<<blocks, 128, DYN_SMEM>>>(x, W1, b1, W2, b2, WLd, bLd, WLo, bLo,
                                       (float4*)d_out, n);
}

// round 13
// speedup vs baseline: 1.6247x; 1.0458x over previous
#include <cuda_runtime.h>
#include <cuda_fp16.h>
#include <cstdint>

typedef unsigned long long ull;

__device__ __forceinline__ ull pack2(float lo, float hi) {
    ull r; asm("mov.b64 %0, {%1, %2};" : "=l"(r) : "f"(lo), "f"(hi)); return r;
}
__device__ __forceinline__ void unpack2(ull v, float& lo, float& hi) {
    asm("mov.b64 {%0, %1}, %2;" : "=f"(lo), "=f"(hi) : "l"(v));
}
__device__ __forceinline__ ull fma2(ull a, ull b, ull c) {
    ull d; asm("fma.rn.f32x2 %0, %1, %2, %3;" : "=l"(d) : "l"(a), "l"(b), "l"(c)); return d;
}
__device__ __forceinline__ float softplus_f(float x) {
    return fmaxf(x, 0.0f) + log1pf(expf(-fabsf(x)));
}
__device__ __forceinline__ uint32_t smem_u32(const void* p) {
    uint32_t a;
    asm("{ .reg .u64 t; cvta.to.shared.u64 t, %1; cvt.u32.u64 %0, t; }" : "=r"(a) : "l"(p));
    return a;
}

#define SW128(off) ((off) ^ (((off) >> 3) & 0x70))

// mma.sync m16n8k16 row.col f32 += f16*f16 (baseline PTX, works on compute_103)
#define MMA16816H(d, a, b0v, b1v) \
    asm volatile("mma.sync.aligned.m16n8k16.row.col.f32.f16.f16.f32 " \
        "{%0,%1,%2,%3}, {%4,%5,%6,%7}, {%8,%9}, {%0,%1,%2,%3};" \
        : "+f"((d)[0]), "+f"((d)[1]), "+f"((d)[2]), "+f"((d)[3]) \
        : "r"((a)[0]), "r"((a)[1]), "r"((a)[2]), "r"((a)[3]), "r"(b0v), "r"(b1v))

static constexpr int DYN_SMEM = 1024 + 8192;   // align pad + W2 fp16 (SW128)

__global__ __launch_bounds__(128, 4)
void dln_mma(const float4* __restrict__ x,
             const float* __restrict__ W1, const float* __restrict__ b1,
             const float* __restrict__ W2, const float* __restrict__ b2,
             const float* __restrict__ WLd, const float* __restrict__ bLd,
             const float* __restrict__ WLo, const float* __restrict__ bLo,
             float4* __restrict__ out, int n)
{
    extern __shared__ char dyn[];
    __shared__ __align__(16) ulonglong2 sW1a[32], sW1b[32];  // (W1[2jp][k],W1[2jp+1][k]) pairs
    __shared__ ull sb1p[32];
    __shared__ ull sB2p[32];                                 // (b2[2jp], b2[2jp+1])
    __shared__ __align__(16) ulonglong2 sHd[32];             // {(Ld0 pair), (Ld1 pair)}
    __shared__ ull sLoP[32];                                 // (WLo pair)
    __shared__ float sbh[4];

    const int tid  = threadIdx.x;
    const int lane = tid & 31;
    const int wid  = tid >> 5;
    const int c    = lane & 3;    // quad col id
    const int rq   = lane >> 2;   // quad row id

    const uint32_t dbase = smem_u32(dyn);
    const uint32_t whi = (dbase + 1023u) & ~1023u;

    // ---- prep: W2 -> fp16 SW128 tile; packed small weights ----
    for (int i = tid; i < 4096; i += 128) {
        float w = W2[i];
        uint16_t hb; asm("cvt.rn.f16.f32 %0, %1;" : "=h"(hb) : "f"(w));
        uint32_t off = SW128((uint32_t)(((i >> 6) * 128) + ((i & 63) * 2)));
        asm volatile("st.shared.u16 [%0], %1;" :: "r"(whi + off), "h"(hb));
    }
    for (int jp = tid; jp < 32; jp += 128) {
        sW1a[jp] = make_ulonglong2(pack2(W1[(2*jp)*4+0], W1[(2*jp+1)*4+0]),
                                   pack2(W1[(2*jp)*4+1], W1[(2*jp+1)*4+1]));
        sW1b[jp] = make_ulonglong2(pack2(W1[(2*jp)*4+2], W1[(2*jp+1)*4+2]),
                                   pack2(W1[(2*jp)*4+3], W1[(2*jp+1)*4+3]));
        sb1p[jp] = pack2(b1[2*jp], b1[2*jp+1]);
        sB2p[jp] = pack2(b2[2*jp], b2[2*jp+1]);
        sHd[jp]  = make_ulonglong2(pack2(WLd[2*jp],    WLd[2*jp+1]),
                                   pack2(WLd[64+2*jp], WLd[64+2*jp+1]));
        sLoP[jp] = pack2(WLo[2*jp], WLo[2*jp+1]);
    }
    if (tid == 0) { sbh[0] = bLd[0]; sbh[1] = bLd[1]; sbh[2] = bLo[0]; sbh[3] = 0.f; }
    __syncthreads();

    const ull SLOPE2 = pack2(0.01f, 0.01f);

    const int ntiles = (n + 127) >> 7;
    for (int t = blockIdx.x; t < ntiles; t += gridDim.x) {
        const int gbase = (t << 7) + (wid << 5);

        // ---- per-thread q rows (rq + 8s), stored unpacked ----
        float qv[16];
        #pragma unroll
        for (int s = 0; s < 4; ++s) {
            int gr = gbase + rq + 8 * s;
            if (gr > n - 1) gr = n - 1;
            float4 q = x[gr];
            qv[4*s+0] = q.x; qv[4*s+1] = q.y; qv[4*s+2] = q.z; qv[4*s+3] = q.w;
        }

        // ---- D init = broadcast b2 (MMA accumulates onto it) ----
        float D[2][8][4];
        #pragma unroll
        for (int nt = 0; nt < 8; ++nt) {
            float e0, e1; unpack2(sB2p[4*nt + c], e0, e1);
            D[0][nt][0] = e0; D[0][nt][1] = e1; D[0][nt][2] = e0; D[0][nt][3] = e1;
            D[1][nt][0] = e0; D[1][nt][1] = e1; D[1][nt][2] = e0; D[1][nt][3] = e1;
        }

        #pragma unroll
        for (int kt = 0; kt < 4; ++kt) {
            // ---- A fragments in place: layer-1 fp32 exact, leaky, fp16 convert ----
            uint32_t af[2][4];
            #pragma unroll
            for (int h = 0; h < 2; ++h) {
                int jp = c + 8 * kt + 4 * h;
                ulonglong2 wA = sW1a[jp], wB = sW1b[jp];
                ull bb = sb1p[jp];
                #pragma unroll
                for (int s = 0; s < 4; ++s) {
                    ull z = fma2(wA.x, pack2(qv[4*s+0], qv[4*s+0]), bb);
                    z = fma2(wA.y, pack2(qv[4*s+1], qv[4*s+1]), z);
                    z = fma2(wB.x, pack2(qv[4*s+2], qv[4*s+2]), z);
                    z = fma2(wB.y, pack2(qv[4*s+3], qv[4*s+3]), z);
                    ull mm = fma2(z, SLOPE2, 0ull);        // 0.01*z packed
                    float z0, z1, m0, m1;
                    unpack2(z, z0, z1); unpack2(mm, m0, m1);
                    float e = fmaxf(z0, m0), o = fmaxf(z1, m1);
                    uint32_t hv;                            // lo half = even col, hi = odd col
                    asm("cvt.rn.f16x2.f32 %0, %1, %2;" : "=r"(hv) : "f"(o), "f"(e));
                    af[s >> 1][2*h + (s & 1)] = hv;
                }
            }

            // ---- B via ldmatrix (fp16), single-product MMA ----
            #pragma unroll
            for (int p = 0; p < 4; ++p) {
                int mat = lane >> 3, rin = lane & 7;
                int nrow = (2*p + (mat >> 1)) * 8 + rin;
                int kseg = 2*kt + (mat & 1);
                uint32_t off = SW128((uint32_t)(nrow * 128 + kseg * 16));
                uint32_t b0, b1v, b2v, b3;
                asm volatile("ldmatrix.sync.aligned.m8n8.x4.shared.b16 {%0,%1,%2,%3}, [%4];"
                    : "=r"(b0), "=r"(b1v), "=r"(b2v), "=r"(b3) : "r"(whi + off));
                MMA16816H(D[0][2*p],     af[0], b0,  b1v);
                MMA16816H(D[1][2*p],     af[1], b0,  b1v);
                MMA16816H(D[0][2*p + 1], af[0], b2v, b3);
                MMA16816H(D[1][2*p + 1], af[1], b2v, b3);
            }
        }

        // ---- packed epilogue: leaky + head dots over column pairs ----
        float rLd0[4], rLd1[4], rLo[4];
        #pragma unroll
        for (int m = 0; m < 2; ++m) {
            ull a0_0 = 0ull, a1_0 = 0ull, a2_0 = 0ull;   // row slot 2m
            ull a0_1 = 0ull, a1_1 = 0ull, a2_1 = 0ull;   // row slot 2m+1
            #pragma unroll
            for (int nt = 0; nt < 8; ++nt) {
                int jp = 4*nt + c;
                ulonglong2 hd = sHd[jp];
                ull lop = sLoP[jp];
                {
                    ull p = pack2(D[m][nt][0], D[m][nt][1]);
                    ull mm = fma2(p, SLOPE2, 0ull);
                    float z0, z1, m0, m1;
                    unpack2(p, z0, z1); unpack2(mm, m0, m1);
                    ull hp = pack2(fmaxf(z0, m0), fmaxf(z1, m1));
                    a0_0 = fma2(hd.x, hp, a0_0);
                    a1_0 = fma2(hd.y, hp, a1_0);
                    a2_0 = fma2(lop,  hp, a2_0);
                }
                {
                    ull p = pack2(D[m][nt][2], D[m][nt][3]);
                    ull mm = fma2(p, SLOPE2, 0ull);
                    float z0, z1, m0, m1;
                    unpack2(p, z0, z1); unpack2(mm, m0, m1);
                    ull hp = pack2(fmaxf(z0, m0), fmaxf(z1, m1));
                    a0_1 = fma2(hd.x, hp, a0_1);
                    a1_1 = fma2(hd.y, hp, a1_1);
                    a2_1 = fma2(lop,  hp, a2_1);
                }
            }
            float u, v;
            unpack2(a0_0, u, v); rLd0[2*m]   = u + v;
            unpack2(a1_0, u, v); rLd1[2*m]   = u + v;
            unpack2(a2_0, u, v); rLo[2*m]    = u + v;
            unpack2(a0_1, u, v); rLd0[2*m+1] = u + v;
            unpack2(a1_1, u, v); rLd1[2*m+1] = u + v;
            unpack2(a2_1, u, v); rLo[2*m+1]  = u + v;
        }

        // ---- quad all-reduce; lane c finalizes row rq + 8c ----
        float v0 = 0.f, v1 = 0.f, v2 = 0.f;
        #pragma unroll
        for (int s = 0; s < 4; ++s) {
            float a0 = rLd0[s], a1 = rLd1[s], a2 = rLo[s];
            #pragma unroll
            for (int msk = 1; msk <= 2; msk <<= 1) {
                a0 += __shfl_xor_sync(0xFFFFFFFFu, a0, msk);
                a1 += __shfl_xor_sync(0xFFFFFFFFu, a1, msk);
                a2 += __shfl_xor_sync(0xFFFFFFFFu, a2, msk);
            }
            if (c == s) { v0 = a0; v1 = a1; v2 = a2; }
        }

        int g = gbase + rq + 8 * c;
        if (g < n) {
            float Ld0 = softplus_f(v0 + sbh[0]);
            float Ld1 = softplus_f(v1 + sbh[1]);
            float Lo  = v2 + sbh[2];
            float H00 = fmaf(Ld0, Ld0, 1e-9f);
            float H01 = Ld0 * Lo;
            float H11 = fmaf(Lo, Lo, fmaf(Ld1, Ld1, 1e-9f));
            out[g] = make_float4(H00, H01, H01, H11);
        }
    }
}

extern "C" void kernel_launch(void* const* d_in, const int* in_sizes, int n_in,
                              void* d_out, int out_size) {
    const float4* x  = (const float4*)d_in[0];
    const float* W1  = (const float*)d_in[1];
    const float* b1  = (const float*)d_in[2];
    const float* W2  = (const float*)d_in[3];
    const float* b2  = (const float*)d_in[4];
    const float* WLd = (const float*)d_in[5];
    const float* bLd = (const float*)d_in[6];
    const float* WLo = (const float*)d_in[7];
    const float* bLo = (const float*)d_in[8];

    int n = in_sizes[0] / 4;
    int ntiles = (n + 127) >> 7;
    int blocks = 608;                  // 4 CTAs x 152 SMs persistent
    if (blocks > ntiles) blocks = ntiles;
    dln_mma<<<blocks, 128, DYN_SMEM>>>(x, W1, b1, W2, b2, WLd, bLd, WLo, bLo,
                                       (float4*)d_out, n);
}

// round 14
// speedup vs baseline: 2.3470x; 1.4446x over previous
#include <cuda_runtime.h>
#include <cuda_fp16.h>
#include <cstdint>

typedef unsigned long long ull;

__device__ __forceinline__ ull pack2(float lo, float hi) {
    ull r; asm("mov.b64 %0, {%1, %2};" : "=l"(r) : "f"(lo), "f"(hi)); return r;
}
__device__ __forceinline__ void unpack2(ull v, float& lo, float& hi) {
    asm("mov.b64 {%0, %1}, %2;" : "=f"(lo), "=f"(hi) : "l"(v));
}
__device__ __forceinline__ ull fma2(ull a, ull b, ull c) {
    ull d; asm("fma.rn.f32x2 %0, %1, %2, %3;" : "=l"(d) : "l"(a), "l"(b), "l"(c)); return d;
}
__device__ __forceinline__ float softplus_f(float x) {
    return fmaxf(x, 0.0f) + log1pf(expf(-fabsf(x)));
}
__device__ __forceinline__ uint32_t smem_u32(const void* p) {
    uint32_t a;
    asm("{ .reg .u64 t; cvta.to.shared.u64 t, %1; cvt.u32.u64 %0, t; }" : "=r"(a) : "l"(p));
    return a;
}
// packed leaky + fp16x2 convert: returns f16x2 {lo=leaky(d0), hi=leaky(d1)}
__device__ __forceinline__ uint32_t cvtleaky2(float d0, float d1, ull SLOPE2) {
    ull p  = pack2(d0, d1);
    ull mm = fma2(p, SLOPE2, 0ull);
    float m0, m1; unpack2(mm, m0, m1);
    float e = fmaxf(d0, m0), o = fmaxf(d1, m1);
    uint32_t r; asm("cvt.rn.f16x2.f32 %0, %1, %2;" : "=r"(r) : "f"(o), "f"(e));
    return r;
}

#define SW128(off) ((off) ^ (((off) >> 3) & 0x70))

// mma.sync m16n8k16 row.col f32 += f16*f16 (baseline PTX, works on compute_103)
#define MMA16816H(d, a, b0v, b1v) \
    asm volatile("mma.sync.aligned.m16n8k16.row.col.f32.f16.f16.f32 " \
        "{%0,%1,%2,%3}, {%4,%5,%6,%7}, {%8,%9}, {%0,%1,%2,%3};" \
        : "+f"((d)[0]), "+f"((d)[1]), "+f"((d)[2]), "+f"((d)[3]) \
        : "r"((a)[0]), "r"((a)[1]), "r"((a)[2]), "r"((a)[3]), "r"(b0v), "r"(b1v))

static constexpr int DYN_SMEM = 1024 + 8192 + 2048;   // pad + W2 fp16 SW128 + W1 fp16 [64][16]

__global__ __launch_bounds__(128, 3)
void dln_mma(const float4* __restrict__ x,
             const float* __restrict__ W1, const float* __restrict__ b1,
             const float* __restrict__ W2, const float* __restrict__ b2,
             const float* __restrict__ WLd, const float* __restrict__ bLd,
             const float* __restrict__ WLo, const float* __restrict__ bLo,
             float4* __restrict__ out, int n)
{
    extern __shared__ char dyn[];
    __shared__ ull sb1p[32];                                 // (b1[2jp], b1[2jp+1])
    __shared__ ull sB2p[32];                                 // (b2[2jp], b2[2jp+1])
    __shared__ __align__(16) ulonglong2 sHd[32];             // {(Ld0 pair), (Ld1 pair)}
    __shared__ ull sLoP[32];                                 // (WLo pair)
    __shared__ float sbh[4];

    const int tid  = threadIdx.x;
    const int lane = tid & 31;
    const int wid  = tid >> 5;
    const int c    = lane & 3;    // quad col id
    const int rq   = lane >> 2;   // quad row id

    const uint32_t dbase = smem_u32(dyn);
    const uint32_t w2t = (dbase + 1023u) & ~1023u;   // W2 fp16, SW128, 64 rows x 128B
    const uint32_t w1t = w2t + 8192u;                // W1 fp16 padded [64][16], 32B rows

    // ---- prep: W2 -> fp16 SW128 tile ----
    for (int i = tid; i < 4096; i += 128) {
        float w = W2[i];
        uint16_t hb; asm("cvt.rn.f16.f32 %0, %1;" : "=h"(hb) : "f"(w));
        uint32_t off = SW128((uint32_t)(((i >> 6) * 128) + ((i & 63) * 2)));
        asm volatile("st.shared.u16 [%0], %1;" :: "r"(w2t + off), "h"(hb));
    }
    // ---- prep: W1 -> fp16 [64 n][16 k] tile, zero-padded k>=4 ----
    for (int i = tid; i < 1024; i += 128) {
        int row = i >> 4, k = i & 15;
        float w = (k < 4) ? W1[row * 4 + k] : 0.0f;
        uint16_t hb; asm("cvt.rn.f16.f32 %0, %1;" : "=h"(hb) : "f"(w));
        asm volatile("st.shared.u16 [%0], %1;" :: "r"(w1t + (uint32_t)(row * 32 + k * 2)), "h"(hb));
    }
    for (int jp = tid; jp < 32; jp += 128) {
        sb1p[jp] = pack2(b1[2*jp], b1[2*jp+1]);
        sB2p[jp] = pack2(b2[2*jp], b2[2*jp+1]);
        sHd[jp]  = make_ulonglong2(pack2(WLd[2*jp],    WLd[2*jp+1]),
                                   pack2(WLd[64+2*jp], WLd[64+2*jp+1]));
        sLoP[jp] = pack2(WLo[2*jp], WLo[2*jp+1]);
    }
    if (tid == 0) { sbh[0] = bLd[0]; sbh[1] = bLd[1]; sbh[2] = bLo[0]; sbh[3] = 0.f; }
    __syncthreads();

    // ---- B1 fragments (W1) loaded ONCE into registers: 8 n-tiles x 2 regs ----
    uint32_t b1f[8][2];
    {
        int mat = lane >> 3, rin = lane & 7;
        #pragma unroll
        for (int g = 0; g < 4; ++g) {
            // matrices: (nt = 2g + (mat>>1), kseg = mat&1)
            uint32_t addr = w1t + (uint32_t)(((2*g + (mat >> 1)) * 8 + rin) * 32 + (mat & 1) * 16);
            uint32_t r0, r1, r2, r3;
            asm volatile("ldmatrix.sync.aligned.m8n8.x4.shared.b16 {%0,%1,%2,%3}, [%4];"
                : "=r"(r0), "=r"(r1), "=r"(r2), "=r"(r3) : "r"(addr));
            b1f[2*g][0] = r0; b1f[2*g][1] = r1;
            b1f[2*g+1][0] = r2; b1f[2*g+1][1] = r3;
        }
    }

    const ull SLOPE2 = pack2(0.01f, 0.01f);

    const int ntiles = (n + 127) >> 7;
    for (int t = blockIdx.x; t < ntiles; t += gridDim.x) {
        const int gbase = (t << 7) + (wid << 5);

        // ---- A1 fragments (q, fp16) built straight from the float4 loads ----
        // A1[m]: rows rq+16m (a0), rq+16m+8 (a1); k = 2c,2c+1 real only for c<2.
        uint32_t A1[2][4];
        #pragma unroll
        for (int m = 0; m < 2; ++m) {
            #pragma unroll
            for (int half = 0; half < 2; ++half) {
                int gr = gbase + rq + 16 * m + 8 * half;
                if (gr > n - 1) gr = n - 1;
                float4 q = x[gr];
                float lo = (c == 0) ? q.x : ((c == 1) ? q.z : 0.0f);
                float hi = (c == 0) ? q.y : ((c == 1) ? q.w : 0.0f);
                uint32_t v; asm("cvt.rn.f16x2.f32 %0, %1, %2;" : "=r"(v) : "f"(hi), "f"(lo));
                A1[m][half] = v;
            }
            A1[m][2] = 0u; A1[m][3] = 0u;   // k >= 8 is padding
        }

        // ---- D2 init = broadcast b2 (layer-2 MMA accumulates onto it) ----
        float D[2][8][4];
        #pragma unroll
        for (int nt = 0; nt < 8; ++nt) {
            float e0, e1; unpack2(sB2p[4*nt + c], e0, e1);
            D[0][nt][0] = e0; D[0][nt][1] = e1; D[0][nt][2] = e0; D[0][nt][3] = e1;
            D[1][nt][0] = e0; D[1][nt][1] = e1; D[1][nt][2] = e0; D[1][nt][3] = e1;
        }

        #pragma unroll
        for (int kt = 0; kt < 4; ++kt) {
            // ---- layer 1 via MMA: h1 cols 16kt..16kt+15 = n-tiles 2kt, 2kt+1 ----
            float D1[2][2][4];
            #pragma unroll
            for (int j = 0; j < 2; ++j) {
                float blo, bhi; unpack2(sb1p[4*(2*kt+j) + c], blo, bhi);
                #pragma unroll
                for (int m = 0; m < 2; ++m) {
                    D1[m][j][0] = blo; D1[m][j][1] = bhi;
                    D1[m][j][2] = blo; D1[m][j][3] = bhi;
                }
            }
            #pragma unroll
            for (int m = 0; m < 2; ++m) {
                MMA16816H(D1[m][0], A1[m], b1f[2*kt][0],   b1f[2*kt][1]);
                MMA16816H(D1[m][1], A1[m], b1f[2*kt+1][0], b1f[2*kt+1][1]);
            }

            // ---- D1 frags ARE layer-2 A frags (same layout): leaky + cvt ----
            uint32_t A2[2][4];
            #pragma unroll
            for (int m = 0; m < 2; ++m) {
                A2[m][0] = cvtleaky2(D1[m][0][0], D1[m][0][1], SLOPE2);  // row rq',  k 2c
                A2[m][1] = cvtleaky2(D1[m][0][2], D1[m][0][3], SLOPE2);  // row rq'+8,k 2c
                A2[m][2] = cvtleaky2(D1[m][1][0], D1[m][1][1], SLOPE2);  // row rq',  k 2c+8
                A2[m][3] = cvtleaky2(D1[m][1][2], D1[m][1][3], SLOPE2);  // row rq'+8,k 2c+8
            }

            // ---- layer 2: B2 via ldmatrix, single-product fp16 MMA ----
            #pragma unroll
            for (int p = 0; p < 4; ++p) {
                int mat = lane >> 3, rin = lane & 7;
                int nrow = (2*p + (mat >> 1)) * 8 + rin;
                int kseg = 2*kt + (mat & 1);
                uint32_t off = SW128((uint32_t)(nrow * 128 + kseg * 16));
                uint32_t b0, b1v, b2v, b3;
                asm volatile("ldmatrix.sync.aligned.m8n8.x4.shared.b16 {%0,%1,%2,%3}, [%4];"
                    : "=r"(b0), "=r"(b1v), "=r"(b2v), "=r"(b3) : "r"(w2t + off));
                MMA16816H(D[0][2*p],     A2[0], b0,  b1v);
                MMA16816H(D[1][2*p],     A2[1], b0,  b1v);
                MMA16816H(D[0][2*p + 1], A2[0], b2v, b3);
                MMA16816H(D[1][2*p + 1], A2[1], b2v, b3);
            }
        }

        // ---- packed epilogue: leaky + head dots over column pairs ----
        float rLd0[4], rLd1[4], rLo[4];
        #pragma unroll
        for (int m = 0; m < 2; ++m) {
            ull a0_0 = 0ull, a1_0 = 0ull, a2_0 = 0ull;   // row slot 2m
            ull a0_1 = 0ull, a1_1 = 0ull, a2_1 = 0ull;   // row slot 2m+1
            #pragma unroll
            for (int nt = 0; nt < 8; ++nt) {
                int jp = 4*nt + c;
                ulonglong2 hd = sHd[jp];
                ull lop = sLoP[jp];
                {
                    ull p = pack2(D[m][nt][0], D[m][nt][1]);
                    ull mm = fma2(p, SLOPE2, 0ull);
                    float z0, z1, m0, m1;
                    unpack2(p, z0, z1); unpack2(mm, m0, m1);
                    ull hp = pack2(fmaxf(z0, m0), fmaxf(z1, m1));
                    a0_0 = fma2(hd.x, hp, a0_0);
                    a1_0 = fma2(hd.y, hp, a1_0);
                    a2_0 = fma2(lop,  hp, a2_0);
                }
                {
                    ull p = pack2(D[m][nt][2], D[m][nt][3]);
                    ull mm = fma2(p, SLOPE2, 0ull);
                    float z0, z1, m0, m1;
                    unpack2(p, z0, z1); unpack2(mm, m0, m1);
                    ull hp = pack2(fmaxf(z0, m0), fmaxf(z1, m1));
                    a0_1 = fma2(hd.x, hp, a0_1);
                    a1_1 = fma2(hd.y, hp, a1_1);
                    a2_1 = fma2(lop,  hp, a2_1);
                }
            }
            float u, v;
            unpack2(a0_0, u, v); rLd0[2*m]   = u + v;
            unpack2(a1_0, u, v); rLd1[2*m]   = u + v;
            unpack2(a2_0, u, v); rLo[2*m]    = u + v;
            unpack2(a0_1, u, v); rLd0[2*m+1] = u + v;
            unpack2(a1_1, u, v); rLd1[2*m+1] = u + v;
            unpack2(a2_1, u, v); rLo[2*m+1]  = u + v;
        }

        // ---- quad all-reduce; lane c finalizes row rq + 8c ----
        float v0 = 0.f, v1 = 0.f, v2 = 0.f;
        #pragma unroll
        for (int s = 0; s < 4; ++s) {
            float a0 = rLd0[s], a1 = rLd1[s], a2 = rLo[s];
            #pragma unroll
            for (int msk = 1; msk <= 2; msk <<= 1) {
                a0 += __shfl_xor_sync(0xFFFFFFFFu, a0, msk);
                a1 += __shfl_xor_sync(0xFFFFFFFFu, a1, msk);
                a2 += __shfl_xor_sync(0xFFFFFFFFu, a2, msk);
            }
            if (c == s) { v0 = a0; v1 = a1; v2 = a2; }
        }

        int g = gbase + rq + 8 * c;
        if (g < n) {
            float Ld0 = softplus_f(v0 + sbh[0]);
            float Ld1 = softplus_f(v1 + sbh[1]);
            float Lo  = v2 + sbh[2];
            float H00 = fmaf(Ld0, Ld0, 1e-9f);
            float H01 = Ld0 * Lo;
            float H11 = fmaf(Lo, Lo, fmaf(Ld1, Ld1, 1e-9f));
            out[g] = make_float4(H00, H01, H01, H11);
        }
    }
}

extern "C" void kernel_launch(void* const* d_in, const int* in_sizes, int n_in,
                              void* d_out, int out_size) {
    const float4* x  = (const float4*)d_in[0];
    const float* W1  = (const float*)d_in[1];
    const float* b1  = (const float*)d_in[2];
    const float* W2  = (const float*)d_in[3];
    const float* b2  = (const float*)d_in[4];
    const float* WLd = (const float*)d_in[5];
    const float* bLd = (const float*)d_in[6];
    const float* WLo = (const float*)d_in[7];
    const float* bLo = (const float*)d_in[8];

    int n = in_sizes[0] / 4;
    int ntiles = (n + 127) >> 7;
    int blocks = 456;                  // 3 CTAs x 152 SMs persistent
    if (blocks > ntiles) blocks = ntiles;
    dln_mma<<<blocks, 128, DYN_SMEM>>>(x, W1, b1, W2, b2, WLd, bLd, WLo, bLo,
                                       (float4*)d_out, n);
}

// round 16
// speedup vs baseline: 2.4476x; 1.0429x over previous
#include <cuda_runtime.h>
#include <cuda_fp16.h>
#include <cstdint>

typedef unsigned long long ull;

__device__ __forceinline__ ull pack2(float lo, float hi) {
    ull r; asm("mov.b64 %0, {%1, %2};" : "=l"(r) : "f"(lo), "f"(hi)); return r;
}
__device__ __forceinline__ void unpack2(ull v, float& lo, float& hi) {
    asm("mov.b64 {%0, %1}, %2;" : "=f"(lo), "=f"(hi) : "l"(v));
}
__device__ __forceinline__ ull fma2(ull a, ull b, ull c) {
    ull d; asm("fma.rn.f32x2 %0, %1, %2, %3;" : "=l"(d) : "l"(a), "l"(b), "l"(c)); return d;
}
__device__ __forceinline__ float softplus_f(float x) {
    return fmaxf(x, 0.0f) + log1pf(expf(-fabsf(x)));
}
__device__ __forceinline__ uint32_t smem_u32(const void* p) {
    uint32_t a;
    asm("{ .reg .u64 t; cvta.to.shared.u64 t, %1; cvt.u32.u64 %0, t; }" : "=r"(a) : "l"(p));
    return a;
}
// packed leaky + fp16x2 convert: returns f16x2 {lo=leaky(d0), hi=leaky(d1)}
__device__ __forceinline__ uint32_t cvtleaky2(float d0, float d1, ull SLOPE2) {
    ull p  = pack2(d0, d1);
    ull mm = fma2(p, SLOPE2, 0ull);
    float m0, m1; unpack2(mm, m0, m1);
    float e = fmaxf(d0, m0), o = fmaxf(d1, m1);
    uint32_t r; asm("cvt.rn.f16x2.f32 %0, %1, %2;" : "=r"(r) : "f"(o), "f"(e));
    return r;
}

#define SW128(off) ((off) ^ (((off) >> 3) & 0x70))

// mma.sync m16n8k16 row.col f32 += f16*f16 (baseline PTX, works on compute_103)
#define MMA16816H(d, a, b0v, b1v) \
    asm volatile("mma.sync.aligned.m16n8k16.row.col.f32.f16.f16.f32 " \
        "{%0,%1,%2,%3}, {%4,%5,%6,%7}, {%8,%9}, {%0,%1,%2,%3};" \
        : "+f"((d)[0]), "+f"((d)[1]), "+f"((d)[2]), "+f"((d)[3]) \
        : "r"((a)[0]), "r"((a)[1]), "r"((a)[2]), "r"((a)[3]), "r"(b0v), "r"(b1v))

static constexpr int DYN_SMEM = 1024 + 8192 + 2048;   // pad + W2 fp16 SW128 + W1 fp16 [64][16]

__global__ __launch_bounds__(128, 4)
void dln_mma(const float4* __restrict__ x,
             const float* __restrict__ W1, const float* __restrict__ b1,
             const float* __restrict__ W2, const float* __restrict__ b2,
             const float* __restrict__ WLd, const float* __restrict__ bLd,
             const float* __restrict__ WLo, const float* __restrict__ bLo,
             float4* __restrict__ out, int n)
{
    extern __shared__ char dyn[];
    __shared__ ull sb1p[32];                                 // (b1[2jp], b1[2jp+1])
    __shared__ ull sB2p[32];                                 // (b2[2jp], b2[2jp+1])
    __shared__ __align__(16) ulonglong2 sHd[32];             // {(Ld0 pair), (Ld1 pair)}
    __shared__ ull sLoP[32];                                 // (WLo pair)
    __shared__ float sbh[4];

    const int tid  = threadIdx.x;
    const int lane = tid & 31;
    const int wid  = tid >> 5;
    const int c    = lane & 3;    // quad col id
    const int rq   = lane >> 2;   // quad row id

    const uint32_t dbase = smem_u32(dyn);
    const uint32_t w2t = (dbase + 1023u) & ~1023u;   // W2 fp16, SW128, 64 rows x 128B
    const uint32_t w1t = w2t + 8192u;                // W1 fp16 padded [64][16], 32B rows

    // ---- prep: W2 -> fp16 SW128 tile ----
    for (int i = tid; i < 4096; i += 128) {
        float w = W2[i];
        uint16_t hb; asm("cvt.rn.f16.f32 %0, %1;" : "=h"(hb) : "f"(w));
        uint32_t off = SW128((uint32_t)(((i >> 6) * 128) + ((i & 63) * 2)));
        asm volatile("st.shared.u16 [%0], %1;" :: "r"(w2t + off), "h"(hb));
    }
    // ---- prep: W1 -> fp16 [64 n][16 k] tile, zero-padded k>=4 ----
    for (int i = tid; i < 1024; i += 128) {
        int row = i >> 4, k = i & 15;
        float w = (k < 4) ? W1[row * 4 + k] : 0.0f;
        uint16_t hb; asm("cvt.rn.f16.f32 %0, %1;" : "=h"(hb) : "f"(w));
        asm volatile("st.shared.u16 [%0], %1;" :: "r"(w1t + (uint32_t)(row * 32 + k * 2)), "h"(hb));
    }
    for (int jp = tid; jp < 32; jp += 128) {
        sb1p[jp] = pack2(b1[2*jp], b1[2*jp+1]);
        sB2p[jp] = pack2(b2[2*jp], b2[2*jp+1]);
        sHd[jp]  = make_ulonglong2(pack2(WLd[2*jp],    WLd[2*jp+1]),
                                   pack2(WLd[64+2*jp], WLd[64+2*jp+1]));
        sLoP[jp] = pack2(WLo[2*jp], WLo[2*jp+1]);
    }
    if (tid == 0) { sbh[0] = bLd[0]; sbh[1] = bLd[1]; sbh[2] = bLo[0]; sbh[3] = 0.f; }
    __syncthreads();

    const ull SLOPE2 = pack2(0.01f, 0.01f);

    // W1 ldmatrix address for per-kt fragment loads:
    // x4 matrices map to (nt = 2kt + (mat>>1), kseg = mat&1)
    const int mat = lane >> 3, rin = lane & 7;
    const uint32_t w1addr_base = w1t + (uint32_t)(((mat >> 1) * 8 + rin) * 32 + (mat & 1) * 16);

    const int ntiles = (n + 127) >> 7;
    for (int t = blockIdx.x; t < ntiles; t += gridDim.x) {
        const int gbase = (t << 7) + (wid << 5);

        // ---- A1 fragments (q, fp16) built straight from the float4 loads ----
        uint32_t A1[2][4];
        #pragma unroll
        for (int m = 0; m < 2; ++m) {
            #pragma unroll
            for (int half = 0; half < 2; ++half) {
                int gr = gbase + rq + 16 * m + 8 * half;
                if (gr > n - 1) gr = n - 1;
                float4 q = x[gr];
                float lo = (c == 0) ? q.x : ((c == 1) ? q.z : 0.0f);
                float hi = (c == 0) ? q.y : ((c == 1) ? q.w : 0.0f);
                uint32_t v; asm("cvt.rn.f16x2.f32 %0, %1, %2;" : "=r"(v) : "f"(hi), "f"(lo));
                A1[m][half] = v;
            }
            A1[m][2] = 0u; A1[m][3] = 0u;   // k >= 8 is padding
        }

        // ---- D2 init = broadcast b2 (layer-2 MMA accumulates onto it) ----
        float D[2][8][4];
        #pragma unroll
        for (int nt = 0; nt < 8; ++nt) {
            float e0, e1; unpack2(sB2p[4*nt + c], e0, e1);
            D[0][nt][0] = e0; D[0][nt][1] = e1; D[0][nt][2] = e0; D[0][nt][3] = e1;
            D[1][nt][0] = e0; D[1][nt][1] = e1; D[1][nt][2] = e0; D[1][nt][3] = e1;
        }

        #pragma unroll
        for (int kt = 0; kt < 4; ++kt) {
            // ---- W1 B-fragments for this kt (one ldmatrix.x4: n-tiles 2kt, 2kt+1) ----
            uint32_t bw0, bw1, bw2, bw3;
            {
                uint32_t addr = w1addr_base + (uint32_t)(kt * 16 * 32);   // +16 n-rows per kt
                asm volatile("ldmatrix.sync.aligned.m8n8.x4.shared.b16 {%0,%1,%2,%3}, [%4];"
                    : "=r"(bw0), "=r"(bw1), "=r"(bw2), "=r"(bw3) : "r"(addr));
            }

            // ---- layer 1 via MMA: h1 cols 16kt..16kt+15 = n-tiles 2kt, 2kt+1 ----
            float D1[2][2][4];
            #pragma unroll
            for (int j = 0; j < 2; ++j) {
                float blo, bhi; unpack2(sb1p[4*(2*kt+j) + c], blo, bhi);
                #pragma unroll
                for (int m = 0; m < 2; ++m) {
                    D1[m][j][0] = blo; D1[m][j][1] = bhi;
                    D1[m][j][2] = blo; D1[m][j][3] = bhi;
                }
            }
            #pragma unroll
            for (int m = 0; m < 2; ++m) {
                MMA16816H(D1[m][0], A1[m], bw0, bw1);
                MMA16816H(D1[m][1], A1[m], bw2, bw3);
            }

            // ---- D1 frags ARE layer-2 A frags (same layout): leaky + cvt ----
            uint32_t A2[2][4];
            #pragma unroll
            for (int m = 0; m < 2; ++m) {
                A2[m][0] = cvtleaky2(D1[m][0][0], D1[m][0][1], SLOPE2);
                A2[m][1] = cvtleaky2(D1[m][0][2], D1[m][0][3], SLOPE2);
                A2[m][2] = cvtleaky2(D1[m][1][0], D1[m][1][1], SLOPE2);
                A2[m][3] = cvtleaky2(D1[m][1][2], D1[m][1][3], SLOPE2);
            }

            // ---- layer 2: B2 via ldmatrix, single-product fp16 MMA ----
            #pragma unroll
            for (int p = 0; p < 4; ++p) {
                int nrow = (2*p + (mat >> 1)) * 8 + rin;
                int kseg = 2*kt + (mat & 1);
                uint32_t off = SW128((uint32_t)(nrow * 128 + kseg * 16));
                uint32_t b0, b1v, b2v, b3;
                asm volatile("ldmatrix.sync.aligned.m8n8.x4.shared.b16 {%0,%1,%2,%3}, [%4];"
                    : "=r"(b0), "=r"(b1v), "=r"(b2v), "=r"(b3) : "r"(w2t + off));
                MMA16816H(D[0][2*p],     A2[0], b0,  b1v);
                MMA16816H(D[1][2*p],     A2[1], b0,  b1v);
                MMA16816H(D[0][2*p + 1], A2[0], b2v, b3);
                MMA16816H(D[1][2*p + 1], A2[1], b2v, b3);
            }
        }

        // ---- packed epilogue: leaky + head dots over column pairs ----
        float rLd0[4], rLd1[4], rLo[4];
        #pragma unroll
        for (int m = 0; m < 2; ++m) {
            ull a0_0 = 0ull, a1_0 = 0ull, a2_0 = 0ull;   // row slot 2m
            ull a0_1 = 0ull, a1_1 = 0ull, a2_1 = 0ull;   // row slot 2m+1
            #pragma unroll
            for (int nt = 0; nt < 8; ++nt) {
                int jp = 4*nt + c;
                ulonglong2 hd = sHd[jp];
                ull lop = sLoP[jp];
                {
                    ull p = pack2(D[m][nt][0], D[m][nt][1]);
                    ull mm = fma2(p, SLOPE2, 0ull);
                    float z0, z1, m0, m1;
                    unpack2(p, z0, z1); unpack2(mm, m0, m1);
                    ull hp = pack2(fmaxf(z0, m0), fmaxf(z1, m1));
                    a0_0 = fma2(hd.x, hp, a0_0);
                    a1_0 = fma2(hd.y, hp, a1_0);
                    a2_0 = fma2(lop,  hp, a2_0);
                }
                {
                    ull p = pack2(D[m][nt][2], D[m][nt][3]);
                    ull mm = fma2(p, SLOPE2, 0ull);
                    float z0, z1, m0, m1;
                    unpack2(p, z0, z1); unpack2(mm, m0, m1);
                    ull hp = pack2(fmaxf(z0, m0), fmaxf(z1, m1));
                    a0_1 = fma2(hd.x, hp, a0_1);
                    a1_1 = fma2(hd.y, hp, a1_1);
                    a2_1 = fma2(lop,  hp, a2_1);
                }
            }
            float u, v;
            unpack2(a0_0, u, v); rLd0[2*m]   = u + v;
            unpack2(a1_0, u, v); rLd1[2*m]   = u + v;
            unpack2(a2_0, u, v); rLo[2*m]    = u + v;
            unpack2(a0_1, u, v); rLd0[2*m+1] = u + v;
            unpack2(a1_1, u, v); rLd1[2*m+1] = u + v;
            unpack2(a2_1, u, v); rLo[2*m+1]  = u + v;
        }

        // ---- quad all-reduce; lane c finalizes row rq + 8c ----
        float v0 = 0.f, v1 = 0.f, v2 = 0.f;
        #pragma unroll
        for (int s = 0; s < 4; ++s) {
            float a0 = rLd0[s], a1 = rLd1[s], a2 = rLo[s];
            #pragma unroll
            for (int msk = 1; msk <= 2; msk <<= 1) {
                a0 += __shfl_xor_sync(0xFFFFFFFFu, a0, msk);
                a1 += __shfl_xor_sync(0xFFFFFFFFu, a1, msk);
                a2 += __shfl_xor_sync(0xFFFFFFFFu, a2, msk);
            }
            if (c == s) { v0 = a0; v1 = a1; v2 = a2; }
        }

        int g = gbase + rq + 8 * c;
        if (g < n) {
            float Ld0 = softplus_f(v0 + sbh[0]);
            float Ld1 = softplus_f(v1 + sbh[1]);
            float Lo  = v2 + sbh[2];
            float H00 = fmaf(Ld0, Ld0, 1e-9f);
            float H01 = Ld0 * Lo;
            float H11 = fmaf(Lo, Lo, fmaf(Ld1, Ld1, 1e-9f));
            out[g] = make_float4(H00, H01, H01, H11);
        }
    }
}

extern "C" void kernel_launch(void* const* d_in, const int* in_sizes, int n_in,
                              void* d_out, int out_size) {
    const float4* x  = (const float4*)d_in[0];
    const float* W1  = (const float*)d_in[1];
    const float* b1  = (const float*)d_in[2];
    const float* W2  = (const float*)d_in[3];
    const float* b2  = (const float*)d_in[4];
    const float* WLd = (const float*)d_in[5];
    const float* bLd = (const float*)d_in[6];
    const float* WLo = (const float*)d_in[7];
    const float* bLo = (const float*)d_in[8];

    int n = in_sizes[0] / 4;
    int ntiles = (n + 127) >> 7;
    int blocks = 608;                  // 4 CTAs x 152 SMs persistent
    if (blocks > ntiles) blocks = ntiles;
    dln_mma<<<blocks, 128, DYN_SMEM>>>(x, W1, b1, W2, b2, WLd, bLd, WLo, bLo,
                                       (float4*)d_out, n);
}